// round 1
// baseline (speedup 1.0000x reference)
#include <cuda_runtime.h>
#include <math.h>

#define B     4096
#define D     512
#define NROW  8192      // 2B
#define TS    128       // output tile
#define KS    16        // k chunk
#define SST   17        // smem stride (conflict-free)

// Scratch (allocation-free rule: __device__ globals)
__device__ float g_x[NROW * D];       // normalized [e1;e2], 16 MB
__device__ float g_inv_t[NROW];
__device__ float g_pos[NROW];
__device__ float g_denom[NROW];

__device__ __forceinline__ float blockReduce256(float v, float* sbuf) {
    int t = threadIdx.x;
    #pragma unroll
    for (int o = 16; o > 0; o >>= 1) v += __shfl_xor_sync(0xFFFFFFFFu, v, o);
    if ((t & 31) == 0) sbuf[t >> 5] = v;
    __syncthreads();
    if (t < 32) {
        float r = (t < 8) ? sbuf[t] : 0.0f;
        #pragma unroll
        for (int o = 4; o > 0; o >>= 1) r += __shfl_xor_sync(0xFFFFFFFFu, r, o);
        if (t == 0) sbuf[0] = r;
    }
    __syncthreads();
    float r = sbuf[0];
    __syncthreads();
    return r;
}

// One CTA per batch row b: normalize e1_b, e2_b, compute att mean -> inv temp,
// pos_sim, zero denom.
__global__ void __launch_bounds__(256) prep_kernel(const float* __restrict__ emb1,
                                                   const float* __restrict__ emb2,
                                                   const float* __restrict__ att) {
    __shared__ float sbuf[8];
    int b = blockIdx.x;
    int t = threadIdx.x;
    const float* a = emb1 + (size_t)b * D;
    const float* c = emb2 + (size_t)b * D;
    float a0 = a[t], a1 = a[t + 256];
    float c0 = c[t], c1 = c[t + 256];
    float s1 = blockReduce256(a0 * a0 + a1 * a1, sbuf);
    float s2 = blockReduce256(c0 * c0 + c1 * c1, sbuf);
    float sd = blockReduce256(a0 * c0 + a1 * c1, sbuf);
    float sa = blockReduce256(att[(size_t)b * 256 + t], sbuf);

    float n1 = fmaxf(sqrtf(s1), 1e-12f);
    float n2 = fmaxf(sqrtf(s2), 1e-12f);
    float r1 = 1.0f / n1, r2 = 1.0f / n2;
    float temp = 0.07f * (1.0f + 0.5f * (sa * (1.0f / 256.0f)));
    float invt = 1.0f / temp;

    float* x1 = g_x + (size_t)b * D;
    float* x2 = g_x + (size_t)(b + B) * D;
    x1[t] = a0 * r1;  x1[t + 256] = a1 * r1;
    x2[t] = c0 * r2;  x2[t + 256] = c1 * r2;

    if (t == 0) {
        g_inv_t[b] = invt;  g_inv_t[b + B] = invt;
        float p = sd * r1 * r2 * invt;
        g_pos[b] = p;       g_pos[b + B] = p;
        g_denom[b] = 0.0f;  g_denom[b + B] = 0.0f;
    }
}

// 128x128 tile of G = x x^T, fused exp(sim)/rowsum epilogue.
// 256 threads, 8x8 microtile, strided (rows = ty+16r, cols = tx+16c) so
// As reads broadcast and Bs reads are bank-conflict-free with stride 17.
__global__ void __launch_bounds__(256, 2) gemm_exp_kernel() {
    __shared__ float As[TS][SST];
    __shared__ float Bs[TS][SST];
    int ti = blockIdx.y, tj = blockIdx.x;
    int tid = threadIdx.x;
    int tx = tid & 15, ty = tid >> 4;

    const float* Xa = g_x + (size_t)ti * TS * D;
    const float* Xb = g_x + (size_t)tj * TS * D;

    float acc[8][8];
    #pragma unroll
    for (int r = 0; r < 8; r++)
        #pragma unroll
        for (int c = 0; c < 8; c++) acc[r][c] = 0.0f;

    int lrow = tid >> 2;         // 0..63
    int lk   = (tid & 3) * 4;    // 0,4,8,12

    for (int k0 = 0; k0 < D; k0 += KS) {
        __syncthreads();
        #pragma unroll
        for (int l = 0; l < 2; l++) {
            int row = lrow + l * 64;
            float4 va = *(const float4*)(Xa + (size_t)row * D + k0 + lk);
            As[row][lk + 0] = va.x; As[row][lk + 1] = va.y;
            As[row][lk + 2] = va.z; As[row][lk + 3] = va.w;
            float4 vb = *(const float4*)(Xb + (size_t)row * D + k0 + lk);
            Bs[row][lk + 0] = vb.x; Bs[row][lk + 1] = vb.y;
            Bs[row][lk + 2] = vb.z; Bs[row][lk + 3] = vb.w;
        }
        __syncthreads();
        #pragma unroll
        for (int k = 0; k < KS; k++) {
            float ar[8], br[8];
            #pragma unroll
            for (int r = 0; r < 8; r++) ar[r] = As[ty + 16 * r][k];
            #pragma unroll
            for (int c = 0; c < 8; c++) br[c] = Bs[tx + 16 * c][k];
            #pragma unroll
            for (int r = 0; r < 8; r++)
                #pragma unroll
                for (int c = 0; c < 8; c++)
                    acc[r][c] = fmaf(ar[r], br[c], acc[r][c]);
        }
    }

    // Epilogue: sim = acc * inv_t[row]; mask diag; exp; rowsum; atomic to denom
    int ibase = ti * TS + ty;
    int jbase = tj * TS + tx;
    #pragma unroll
    for (int r = 0; r < 8; r++) {
        int gi = ibase + 16 * r;
        float invt = g_inv_t[gi];
        float s = 0.0f;
        #pragma unroll
        for (int c = 0; c < 8; c++) {
            int gj = jbase + 16 * c;
            float e = __expf(acc[r][c] * invt);
            if (gi == gj) e = 0.0f;   // diag -> -inf -> exp = 0
            s += e;
        }
        // reduce across the 16 tx lanes (lane bits 0..3)
        s += __shfl_xor_sync(0xFFFFFFFFu, s, 1);
        s += __shfl_xor_sync(0xFFFFFFFFu, s, 2);
        s += __shfl_xor_sync(0xFFFFFFFFu, s, 4);
        s += __shfl_xor_sync(0xFFFFFFFFu, s, 8);
        if (tx == 0) atomicAdd(&g_denom[gi], s);
    }
}

__global__ void __launch_bounds__(256) final_kernel(float* __restrict__ out) {
    __shared__ float sbuf[8];
    float s = 0.0f;
    for (int i = threadIdx.x; i < NROW; i += 256)
        s += logf(g_denom[i]) - g_pos[i];
    float tot = blockReduce256(s, sbuf);
    if (threadIdx.x == 0) out[0] = tot * (1.0f / NROW);
}

extern "C" void kernel_launch(void* const* d_in, const int* in_sizes, int n_in,
                              void* d_out, int out_size) {
    const float* emb1 = (const float*)d_in[0];
    const float* emb2 = (const float*)d_in[1];
    const float* att  = (const float*)d_in[2];

    prep_kernel<<<B, 256>>>(emb1, emb2, att);
    dim3 grid(NROW / TS, NROW / TS);   // 64 x 64 tiles
    gemm_exp_kernel<<<grid, 256>>>();
    final_kernel<<<1, 256>>>((float*)d_out);
}

// round 5
// speedup vs baseline: 12.6740x; 12.6740x over previous
#include <cuda_runtime.h>
#include <cuda_bf16.h>
#include <math.h>
#include <stdint.h>

#define BATCH 4096
#define D     512
#define NROW  8192          // 2B
#define TS    128           // CTA tile (square)
#define KC    64            // k chunk in bf16 elems = 128 bytes/row
#define NCH   (D / KC)      // 8 chunks
#define AB_BYTES (TS * 128)            // 16384 per operand per stage
#define STAGE_BYTES (2 * AB_BYTES)     // 32768
#define SMEM_TOTAL (2 * STAGE_BYTES)   // 65536

// ---- scratch (__device__ globals: allocation-free rule) ----
__device__ __nv_bfloat16 g_xb[NROW * D];   // normalized [e1;e2] bf16, 8 MB
__device__ float g_inv_t[NROW];
__device__ float g_pos[NROW];
__device__ float g_denom[NROW];

__device__ __forceinline__ uint32_t smem_u32(const void* p) {
    uint32_t a;
    asm("{ .reg .u64 t; cvta.to.shared.u64 t, %1; cvt.u32.u64 %0, t; }"
        : "=r"(a) : "l"(p));
    return a;
}
__device__ __forceinline__ void cp_async16(uint32_t dst, const void* src) {
    asm volatile("cp.async.cg.shared.global [%0], [%1], 16;"
                 :: "r"(dst), "l"(src) : "memory");
}
#define CP_COMMIT() asm volatile("cp.async.commit_group;" ::: "memory")

#define LDM_X4(r, addr)                                                     \
    asm volatile("ldmatrix.sync.aligned.m8n8.x4.shared.b16 {%0,%1,%2,%3}, [%4];" \
                 : "=r"(r[0]), "=r"(r[1]), "=r"(r[2]), "=r"(r[3]) : "r"(addr))

#define MMA16816(d, a, b)                                                   \
    asm volatile("mma.sync.aligned.m16n8k16.row.col.f32.bf16.bf16.f32 "     \
                 "{%0,%1,%2,%3}, {%4,%5,%6,%7}, {%8,%9}, {%0,%1,%2,%3};"    \
                 : "+f"(d[0]), "+f"(d[1]), "+f"(d[2]), "+f"(d[3])           \
                 : "r"(a[0]), "r"(a[1]), "r"(a[2]), "r"(a[3]),              \
                   "r"(b[0]), "r"(b[1]))

// ---- prep: normalize, temps, pos_sim, zero denom, write bf16 x ----
__device__ __forceinline__ float blockReduce256(float v, float* sbuf) {
    int t = threadIdx.x;
    #pragma unroll
    for (int o = 16; o > 0; o >>= 1) v += __shfl_xor_sync(0xFFFFFFFFu, v, o);
    if ((t & 31) == 0) sbuf[t >> 5] = v;
    __syncthreads();
    if (t < 32) {
        float r = (t < 8) ? sbuf[t] : 0.0f;
        #pragma unroll
        for (int o = 4; o > 0; o >>= 1) r += __shfl_xor_sync(0xFFFFFFFFu, r, o);
        if (t == 0) sbuf[0] = r;
    }
    __syncthreads();
    float r = sbuf[0];
    __syncthreads();
    return r;
}

__global__ void __launch_bounds__(256) prep_kernel(const float* __restrict__ emb1,
                                                   const float* __restrict__ emb2,
                                                   const float* __restrict__ att) {
    __shared__ float sbuf[8];
    int b = blockIdx.x;
    int t = threadIdx.x;
    const float* a = emb1 + (size_t)b * D;
    const float* c = emb2 + (size_t)b * D;
    float a0 = a[t], a1 = a[t + 256];
    float c0 = c[t], c1 = c[t + 256];
    float s1 = blockReduce256(a0 * a0 + a1 * a1, sbuf);
    float s2 = blockReduce256(c0 * c0 + c1 * c1, sbuf);
    float sd = blockReduce256(a0 * c0 + a1 * c1, sbuf);
    float sa = blockReduce256(att[(size_t)b * 256 + t], sbuf);

    float r1 = 1.0f / fmaxf(sqrtf(s1), 1e-12f);
    float r2 = 1.0f / fmaxf(sqrtf(s2), 1e-12f);
    float invt = 1.0f / (0.07f * (1.0f + 0.5f * (sa * (1.0f / 256.0f))));

    __nv_bfloat16* x1 = g_xb + (size_t)b * D;
    __nv_bfloat16* x2 = g_xb + (size_t)(b + BATCH) * D;
    x1[t] = __float2bfloat16(a0 * r1);  x1[t + 256] = __float2bfloat16(a1 * r1);
    x2[t] = __float2bfloat16(c0 * r2);  x2[t + 256] = __float2bfloat16(c1 * r2);

    if (t == 0) {
        g_inv_t[b] = invt;  g_inv_t[b + BATCH] = invt;
        float p = sd * r1 * r2 * invt;
        g_pos[b] = p;       g_pos[b + BATCH] = p;
        g_denom[b] = 0.0f;  g_denom[b + BATCH] = 0.0f;
    }
}

// swizzled byte offset within a 128x64-bf16 operand buffer
__device__ __forceinline__ uint32_t swz(int row, int c16) {
    return (uint32_t)(row * 128 + ((c16 ^ (row & 7)) * 16));
}

__device__ __forceinline__ void load_stage(uint32_t sb, int stage,
                                           const __nv_bfloat16* Xa,
                                           const __nv_bfloat16* Xb,
                                           int chunk, int tid) {
    uint32_t base = sb + stage * STAGE_BYTES;
    #pragma unroll
    for (int it = 0; it < 8; it++) {
        int idx = tid + it * 256;          // 0..2047
        int isA = idx < 1024;
        int j = isA ? idx : idx - 1024;
        int row = j >> 3, c16 = j & 7;
        const __nv_bfloat16* src =
            (isA ? Xa : Xb) + (size_t)row * D + chunk * KC + c16 * 8;
        uint32_t dst = base + (isA ? 0u : (uint32_t)AB_BYTES) + swz(row, c16);
        cp_async16(dst, src);
    }
}

// ---- HMMA GEMM tile (128x128) + fused exp row/col-sum epilogue.
// Only tiles ti<=tj are computed (G symmetric); off-diag tiles contribute
// both row sums and column sums.
__global__ void __launch_bounds__(256) gemm_exp_kernel() {
    int ti = blockIdx.y, tj = blockIdx.x;
    if (tj < ti) return;

    extern __shared__ char smem[];
    uint32_t sb = smem_u32(smem);
    int tid = threadIdx.x;
    int wid = tid >> 5, lane = tid & 31;
    int wm = wid >> 2, wn = wid & 3;       // warp tile: rows wm*64, cols wn*32

    const __nv_bfloat16* Xa = g_xb + (size_t)ti * TS * D;
    const __nv_bfloat16* Xb = g_xb + (size_t)tj * TS * D;

    float acc[4][4][4];
    #pragma unroll
    for (int mt = 0; mt < 4; mt++)
        #pragma unroll
        for (int nf = 0; nf < 4; nf++)
            #pragma unroll
            for (int q = 0; q < 4; q++) acc[mt][nf][q] = 0.0f;

    // ldmatrix source addresses (swizzled), per-lane
    int a_row = wm * 64 + (lane & 7) + ((lane >> 3) & 1) * 8;  // + mt*16
    int a_c16h = (lane >> 4);                                   // + k16*2
    int b_row = wn * 32 + (lane & 7) + ((lane >> 4) & 1) * 8;  // + nt2*16
    int b_c16h = ((lane >> 3) & 1);                             // + k16*2

    load_stage(sb, 0, Xa, Xb, 0, tid);
    CP_COMMIT();

    #pragma unroll 1
    for (int c = 0; c < NCH; c++) {
        if (c + 1 < NCH) {
            load_stage(sb, (c + 1) & 1, Xa, Xb, c + 1, tid);
            CP_COMMIT();
            asm volatile("cp.async.wait_group 1;" ::: "memory");
        } else {
            asm volatile("cp.async.wait_group 0;" ::: "memory");
        }
        __syncthreads();

        uint32_t abase = sb + (c & 1) * STAGE_BYTES;
        uint32_t bbase = abase + AB_BYTES;
        #pragma unroll
        for (int k16 = 0; k16 < KC / 16; k16++) {
            uint32_t a_r[4][4], b_r[2][4];
            #pragma unroll
            for (int mt = 0; mt < 4; mt++)
                LDM_X4(a_r[mt], abase + swz(a_row + mt * 16, k16 * 2 + a_c16h));
            #pragma unroll
            for (int nt2 = 0; nt2 < 2; nt2++)
                LDM_X4(b_r[nt2], bbase + swz(b_row + nt2 * 16, k16 * 2 + b_c16h));
            #pragma unroll
            for (int mt = 0; mt < 4; mt++)
                #pragma unroll
                for (int nt2 = 0; nt2 < 2; nt2++) {
                    MMA16816(acc[mt][nt2 * 2 + 0], a_r[mt], (b_r[nt2] + 0));
                    MMA16816(acc[mt][nt2 * 2 + 1], a_r[mt], (b_r[nt2] + 2));
                }
        }
        __syncthreads();
    }

    // ---- epilogue ----
    int lr = lane >> 2;          // 0..7
    int lc = lane & 3;           // 0..3
    int gr0 = ti * TS + wm * 64 + lr;            // + mt*16, +8 for half
    int gc0 = tj * TS + wn * 32 + lc * 2;        // + nf*8, +1

    if (ti == tj) {
        // diagonal tile: row sums only, with diag mask
        #pragma unroll
        for (int mt = 0; mt < 4; mt++) {
            int gi0 = gr0 + mt * 16, gi1 = gi0 + 8;
            float it0 = g_inv_t[gi0], it1 = g_inv_t[gi1];
            float s0 = 0.0f, s1 = 0.0f;
            #pragma unroll
            for (int nf = 0; nf < 4; nf++) {
                int gj = gc0 + nf * 8;
                float e;
                e = __expf(acc[mt][nf][0] * it0); if (gj     == gi0) e = 0.0f; s0 += e;
                e = __expf(acc[mt][nf][1] * it0); if (gj + 1 == gi0) e = 0.0f; s0 += e;
                e = __expf(acc[mt][nf][2] * it1); if (gj     == gi1) e = 0.0f; s1 += e;
                e = __expf(acc[mt][nf][3] * it1); if (gj + 1 == gi1) e = 0.0f; s1 += e;
            }
            s0 += __shfl_xor_sync(0xFFFFFFFFu, s0, 1);
            s0 += __shfl_xor_sync(0xFFFFFFFFu, s0, 2);
            s1 += __shfl_xor_sync(0xFFFFFFFFu, s1, 1);
            s1 += __shfl_xor_sync(0xFFFFFFFFu, s1, 2);
            if (lc == 0) {
                atomicAdd(&g_denom[gi0], s0);
                atomicAdd(&g_denom[gi1], s1);
            }
        }
    } else {
        // off-diagonal: row sums (invt[row]) and col sums (invt[col])
        float colsum[4][2];
        #pragma unroll
        for (int nf = 0; nf < 4; nf++) { colsum[nf][0] = 0.0f; colsum[nf][1] = 0.0f; }

        #pragma unroll
        for (int mt = 0; mt < 4; mt++) {
            int gi0 = gr0 + mt * 16, gi1 = gi0 + 8;
            float it0 = g_inv_t[gi0], it1 = g_inv_t[gi1];
            float s0 = 0.0f, s1 = 0.0f;
            #pragma unroll
            for (int nf = 0; nf < 4; nf++) {
                int gj = gc0 + nf * 8;
                float jt0 = g_inv_t[gj], jt1 = g_inv_t[gj + 1];
                float v0 = acc[mt][nf][0], v1 = acc[mt][nf][1];
                float v2 = acc[mt][nf][2], v3 = acc[mt][nf][3];
                s0 += __expf(v0 * it0) + __expf(v1 * it0);
                s1 += __expf(v2 * it1) + __expf(v3 * it1);
                colsum[nf][0] += __expf(v0 * jt0) + __expf(v2 * jt0);
                colsum[nf][1] += __expf(v1 * jt1) + __expf(v3 * jt1);
            }
            s0 += __shfl_xor_sync(0xFFFFFFFFu, s0, 1);
            s0 += __shfl_xor_sync(0xFFFFFFFFu, s0, 2);
            s1 += __shfl_xor_sync(0xFFFFFFFFu, s1, 1);
            s1 += __shfl_xor_sync(0xFFFFFFFFu, s1, 2);
            if (lc == 0) {
                atomicAdd(&g_denom[gi0], s0);
                atomicAdd(&g_denom[gi1], s1);
            }
        }
        #pragma unroll
        for (int nf = 0; nf < 4; nf++) {
            #pragma unroll
            for (int i = 0; i < 2; i++) {
                float cs = colsum[nf][i];
                cs += __shfl_xor_sync(0xFFFFFFFFu, cs, 4);
                cs += __shfl_xor_sync(0xFFFFFFFFu, cs, 8);
                cs += __shfl_xor_sync(0xFFFFFFFFu, cs, 16);
                if (lr == 0)
                    atomicAdd(&g_denom[gc0 + nf * 8 + i], cs);
            }
        }
    }
}

__global__ void __launch_bounds__(256) final_kernel(float* __restrict__ out) {
    __shared__ float sbuf[8];
    float s = 0.0f;
    for (int i = threadIdx.x; i < NROW; i += 256)
        s += logf(g_denom[i]) - g_pos[i];
    float tot = blockReduce256(s, sbuf);
    if (threadIdx.x == 0) out[0] = tot * (1.0f / NROW);
}

extern "C" void kernel_launch(void* const* d_in, const int* in_sizes, int n_in,
                              void* d_out, int out_size) {
    const float* emb1 = (const float*)d_in[0];
    const float* emb2 = (const float*)d_in[1];
    const float* att  = (const float*)d_in[2];

    cudaFuncSetAttribute(gemm_exp_kernel,
                         cudaFuncAttributeMaxDynamicSharedMemorySize, SMEM_TOTAL);

    prep_kernel<<<BATCH, 256>>>(emb1, emb2, att);
    dim3 grid(NROW / TS, NROW / TS);   // 64 x 64, lower half exits
    gemm_exp_kernel<<<grid, 256, SMEM_TOTAL>>>();
    final_kernel<<<1, 256>>>((float*)d_out);
}

// round 8
// speedup vs baseline: 14.9307x; 1.1781x over previous
#include <cuda_runtime.h>
#include <cuda_bf16.h>
#include <math.h>
#include <stdint.h>

#define BATCH 4096
#define D     512
#define NROW  8192          // 2B
#define TS    128           // CTA tile (square)
#define KC    64            // k chunk in bf16 elems = 128 bytes/row
#define NCH   (D / KC)      // 8 chunks
#define NT    (NROW / TS)   // 64 tiles per dim
#define NTRI  (NT * (NT + 1) / 2)       // 2080 CTAs
#define AB_BYTES (TS * 128)             // 16384 per operand per stage
#define STAGE_BYTES (2 * AB_BYTES)      // 32768
#define NSTAGE 3
#define SMEM_TOTAL (NSTAGE * STAGE_BYTES)  // 98304

// ---- scratch (__device__ globals: allocation-free rule) ----
__device__ __nv_bfloat16 g_xb[NROW * D];   // normalized [e1;e2] bf16, 8 MB
__device__ float g_inv_t[NROW];
__device__ float g_pos[NROW];
__device__ float g_denom[NROW];

__device__ __forceinline__ uint32_t smem_u32(const void* p) {
    uint32_t a;
    asm("{ .reg .u64 t; cvta.to.shared.u64 t, %1; cvt.u32.u64 %0, t; }"
        : "=r"(a) : "l"(p));
    return a;
}
__device__ __forceinline__ void cp_async16(uint32_t dst, const void* src) {
    asm volatile("cp.async.cg.shared.global [%0], [%1], 16;"
                 :: "r"(dst), "l"(src) : "memory");
}
#define CP_COMMIT() asm volatile("cp.async.commit_group;" ::: "memory")

#define LDM_X4(r, addr)                                                     \
    asm volatile("ldmatrix.sync.aligned.m8n8.x4.shared.b16 {%0,%1,%2,%3}, [%4];" \
                 : "=r"(r[0]), "=r"(r[1]), "=r"(r[2]), "=r"(r[3]) : "r"(addr))

#define MMA16816(d, a, b)                                                   \
    asm volatile("mma.sync.aligned.m16n8k16.row.col.f32.bf16.bf16.f32 "     \
                 "{%0,%1,%2,%3}, {%4,%5,%6,%7}, {%8,%9}, {%0,%1,%2,%3};"    \
                 : "+f"(d[0]), "+f"(d[1]), "+f"(d[2]), "+f"(d[3])           \
                 : "r"(a[0]), "r"(a[1]), "r"(a[2]), "r"(a[3]),              \
                   "r"(b[0]), "r"(b[1]))

// ---- prep: warp-per-row, shfl-only reduces ----
__global__ void __launch_bounds__(256) prep_kernel(const float* __restrict__ emb1,
                                                   const float* __restrict__ emb2,
                                                   const float* __restrict__ att) {
    int warp = (blockIdx.x * 256 + threadIdx.x) >> 5;   // 0..4095 (row b)
    int lane = threadIdx.x & 31;
    if (warp >= BATCH) return;
    int b = warp;

    const float4* a4 = (const float4*)(emb1 + (size_t)b * D);
    const float4* c4 = (const float4*)(emb2 + (size_t)b * D);
    const float4* t4 = (const float4*)(att  + (size_t)b * 256);

    float4 av[4], cv[4];
    float s1 = 0.0f, s2 = 0.0f, sd = 0.0f, sa = 0.0f;
    #pragma unroll
    for (int k = 0; k < 4; k++) {
        int f = lane + k * 32;
        av[k] = a4[f]; cv[k] = c4[f];
        s1 += av[k].x*av[k].x + av[k].y*av[k].y + av[k].z*av[k].z + av[k].w*av[k].w;
        s2 += cv[k].x*cv[k].x + cv[k].y*cv[k].y + cv[k].z*cv[k].z + cv[k].w*cv[k].w;
        sd += av[k].x*cv[k].x + av[k].y*cv[k].y + av[k].z*cv[k].z + av[k].w*cv[k].w;
    }
    #pragma unroll
    for (int k = 0; k < 2; k++) {
        float4 v = t4[lane + k * 32];
        sa += v.x + v.y + v.z + v.w;
    }
    #pragma unroll
    for (int o = 16; o > 0; o >>= 1) {
        s1 += __shfl_xor_sync(0xFFFFFFFFu, s1, o);
        s2 += __shfl_xor_sync(0xFFFFFFFFu, s2, o);
        sd += __shfl_xor_sync(0xFFFFFFFFu, sd, o);
        sa += __shfl_xor_sync(0xFFFFFFFFu, sa, o);
    }

    float r1 = 1.0f / fmaxf(sqrtf(s1), 1e-12f);
    float r2 = 1.0f / fmaxf(sqrtf(s2), 1e-12f);
    float invt = 1.0f / (0.07f * (1.0f + 0.5f * (sa * (1.0f / 256.0f))));

    uint2* x1 = (uint2*)(g_xb + (size_t)b * D);
    uint2* x2 = (uint2*)(g_xb + (size_t)(b + BATCH) * D);
    #pragma unroll
    for (int k = 0; k < 4; k++) {
        int f = lane + k * 32;
        __nv_bfloat162 p0 = __floats2bfloat162_rn(av[k].x * r1, av[k].y * r1);
        __nv_bfloat162 p1 = __floats2bfloat162_rn(av[k].z * r1, av[k].w * r1);
        uint2 u; u.x = *(uint32_t*)&p0; u.y = *(uint32_t*)&p1;
        x1[f] = u;
        p0 = __floats2bfloat162_rn(cv[k].x * r2, cv[k].y * r2);
        p1 = __floats2bfloat162_rn(cv[k].z * r2, cv[k].w * r2);
        u.x = *(uint32_t*)&p0; u.y = *(uint32_t*)&p1;
        x2[f] = u;
    }
    if (lane == 0) {
        g_inv_t[b] = invt;  g_inv_t[b + BATCH] = invt;
        float p = sd * r1 * r2 * invt;
        g_pos[b] = p;       g_pos[b + BATCH] = p;
        g_denom[b] = 0.0f;  g_denom[b + BATCH] = 0.0f;
    }
}

// swizzled byte offset within a 128x64-bf16 operand buffer
__device__ __forceinline__ uint32_t swz(int row, int c16) {
    return (uint32_t)(row * 128 + ((c16 ^ (row & 7)) * 16));
}

__device__ __forceinline__ void load_stage(uint32_t base,
                                           const __nv_bfloat16* Xa,
                                           const __nv_bfloat16* Xb,
                                           int chunk, int tid) {
    #pragma unroll
    for (int it = 0; it < 8; it++) {
        int idx = tid + it * 256;          // 0..2047
        int isA = idx < 1024;
        int j = isA ? idx : idx - 1024;
        int row = j >> 3, c16 = j & 7;
        const __nv_bfloat16* src =
            (isA ? Xa : Xb) + (size_t)row * D + chunk * KC + c16 * 8;
        uint32_t dst = base + (isA ? 0u : (uint32_t)AB_BYTES) + swz(row, c16);
        cp_async16(dst, src);
    }
    CP_COMMIT();
}

// ---- HMMA GEMM tile (128x128) + fused exp row/col-sum epilogue ----
__global__ void __launch_bounds__(256, 2) gemm_exp_kernel() {
    // triangular 1D grid -> (ti, tj), ti <= tj
    int idx = blockIdx.x;
    int ti = (int)((129.0f - sqrtf(16641.0f - 8.0f * (float)idx)) * 0.5f);
    while (ti * (129 - ti) / 2 > idx) ti--;
    while ((ti + 1) * (129 - (ti + 1)) / 2 <= idx) ti++;
    int tj = ti + (idx - ti * (129 - ti) / 2);

    extern __shared__ char smem[];
    uint32_t sb = smem_u32(smem);
    int tid = threadIdx.x;
    int wid = tid >> 5, lane = tid & 31;
    int wm = wid >> 2, wn = wid & 3;       // warp tile: rows wm*64, cols wn*32

    const __nv_bfloat16* Xa = g_xb + (size_t)ti * TS * D;
    const __nv_bfloat16* Xb = g_xb + (size_t)tj * TS * D;

    float acc[4][4][4];
    #pragma unroll
    for (int mt = 0; mt < 4; mt++)
        #pragma unroll
        for (int nf = 0; nf < 4; nf++)
            #pragma unroll
            for (int q = 0; q < 4; q++) acc[mt][nf][q] = 0.0f;

    int a_row = wm * 64 + (lane & 7) + ((lane >> 3) & 1) * 8;  // + mt*16
    int a_c16h = (lane >> 4);                                   // + k16*2
    int b_row = wn * 32 + (lane & 7) + ((lane >> 4) & 1) * 8;  // + nt2*16
    int b_c16h = ((lane >> 3) & 1);                             // + k16*2

    load_stage(sb + 0 * STAGE_BYTES, Xa, Xb, 0, tid);
    load_stage(sb + 1 * STAGE_BYTES, Xa, Xb, 1, tid);

    #pragma unroll 1
    for (int c = 0; c < NCH; c++) {
        if (c + 1 < NCH)
            asm volatile("cp.async.wait_group 1;" ::: "memory");
        else
            asm volatile("cp.async.wait_group 0;" ::: "memory");
        __syncthreads();

        if (c + 2 < NCH)
            load_stage(sb + ((c + 2) % NSTAGE) * STAGE_BYTES, Xa, Xb, c + 2, tid);

        uint32_t abase = sb + (c % NSTAGE) * STAGE_BYTES;
        uint32_t bbase = abase + AB_BYTES;
        #pragma unroll
        for (int k16 = 0; k16 < KC / 16; k16++) {
            uint32_t a_r[4][4], b_r[2][4];
            #pragma unroll
            for (int mt = 0; mt < 4; mt++)
                LDM_X4(a_r[mt], abase + swz(a_row + mt * 16, k16 * 2 + a_c16h));
            #pragma unroll
            for (int nt2 = 0; nt2 < 2; nt2++)
                LDM_X4(b_r[nt2], bbase + swz(b_row + nt2 * 16, k16 * 2 + b_c16h));
            #pragma unroll
            for (int mt = 0; mt < 4; mt++)
                #pragma unroll
                for (int nt2 = 0; nt2 < 2; nt2++) {
                    MMA16816(acc[mt][nt2 * 2 + 0], a_r[mt], (b_r[nt2] + 0));
                    MMA16816(acc[mt][nt2 * 2 + 1], a_r[mt], (b_r[nt2] + 2));
                }
        }
        __syncthreads();
    }

    // ---- epilogue ----
    int lr = lane >> 2;          // 0..7
    int lc = lane & 3;           // 0..3
    int gr0 = ti * TS + wm * 64 + lr;            // + mt*16, +8 for half
    int gc0 = tj * TS + wn * 32 + lc * 2;        // + nf*8, +1

    if (ti == tj) {
        #pragma unroll
        for (int mt = 0; mt < 4; mt++) {
            int gi0 = gr0 + mt * 16, gi1 = gi0 + 8;
            float it0 = g_inv_t[gi0], it1 = g_inv_t[gi1];
            float s0 = 0.0f, s1 = 0.0f;
            #pragma unroll
            for (int nf = 0; nf < 4; nf++) {
                int gj = gc0 + nf * 8;
                float e;
                e = __expf(acc[mt][nf][0] * it0); if (gj     == gi0) e = 0.0f; s0 += e;
                e = __expf(acc[mt][nf][1] * it0); if (gj + 1 == gi0) e = 0.0f; s0 += e;
                e = __expf(acc[mt][nf][2] * it1); if (gj     == gi1) e = 0.0f; s1 += e;
                e = __expf(acc[mt][nf][3] * it1); if (gj + 1 == gi1) e = 0.0f; s1 += e;
            }
            s0 += __shfl_xor_sync(0xFFFFFFFFu, s0, 1);
            s0 += __shfl_xor_sync(0xFFFFFFFFu, s0, 2);
            s1 += __shfl_xor_sync(0xFFFFFFFFu, s1, 1);
            s1 += __shfl_xor_sync(0xFFFFFFFFu, s1, 2);
            if (lc == 0) {
                atomicAdd(&g_denom[gi0], s0);
                atomicAdd(&g_denom[gi1], s1);
            }
        }
    } else {
        float colsum[4][2];
        #pragma unroll
        for (int nf = 0; nf < 4; nf++) { colsum[nf][0] = 0.0f; colsum[nf][1] = 0.0f; }

        #pragma unroll
        for (int mt = 0; mt < 4; mt++) {
            int gi0 = gr0 + mt * 16, gi1 = gi0 + 8;
            float it0 = g_inv_t[gi0], it1 = g_inv_t[gi1];
            float s0 = 0.0f, s1 = 0.0f;
            #pragma unroll
            for (int nf = 0; nf < 4; nf++) {
                int gj = gc0 + nf * 8;
                float jt0 = g_inv_t[gj], jt1 = g_inv_t[gj + 1];
                float v0 = acc[mt][nf][0], v1 = acc[mt][nf][1];
                float v2 = acc[mt][nf][2], v3 = acc[mt][nf][3];
                s0 += __expf(v0 * it0) + __expf(v1 * it0);
                s1 += __expf(v2 * it1) + __expf(v3 * it1);
                colsum[nf][0] += __expf(v0 * jt0) + __expf(v2 * jt0);
                colsum[nf][1] += __expf(v1 * jt1) + __expf(v3 * jt1);
            }
            s0 += __shfl_xor_sync(0xFFFFFFFFu, s0, 1);
            s0 += __shfl_xor_sync(0xFFFFFFFFu, s0, 2);
            s1 += __shfl_xor_sync(0xFFFFFFFFu, s1, 1);
            s1 += __shfl_xor_sync(0xFFFFFFFFu, s1, 2);
            if (lc == 0) {
                atomicAdd(&g_denom[gi0], s0);
                atomicAdd(&g_denom[gi1], s1);
            }
        }
        #pragma unroll
        for (int nf = 0; nf < 4; nf++) {
            #pragma unroll
            for (int i = 0; i < 2; i++) {
                float cs = colsum[nf][i];
                cs += __shfl_xor_sync(0xFFFFFFFFu, cs, 4);
                cs += __shfl_xor_sync(0xFFFFFFFFu, cs, 8);
                cs += __shfl_xor_sync(0xFFFFFFFFu, cs, 16);
                if (lr == 0)
                    atomicAdd(&g_denom[gc0 + nf * 8 + i], cs);
            }
        }
    }
}

__global__ void __launch_bounds__(1024) final_kernel(float* __restrict__ out) {
    __shared__ float sbuf[32];
    int t = threadIdx.x;
    float s = 0.0f;
    #pragma unroll
    for (int k = 0; k < NROW / 1024; k++) {
        int i = t + k * 1024;
        s += __logf(g_denom[i]) - g_pos[i];
    }
    #pragma unroll
    for (int o = 16; o > 0; o >>= 1) s += __shfl_xor_sync(0xFFFFFFFFu, s, o);
    if ((t & 31) == 0) sbuf[t >> 5] = s;
    __syncthreads();
    if (t < 32) {
        float r = sbuf[t];
        #pragma unroll
        for (int o = 16; o > 0; o >>= 1) r += __shfl_xor_sync(0xFFFFFFFFu, r, o);
        if (t == 0) out[0] = r * (1.0f / NROW);
    }
}

extern "C" void kernel_launch(void* const* d_in, const int* in_sizes, int n_in,
                              void* d_out, int out_size) {
    const float* emb1 = (const float*)d_in[0];
    const float* emb2 = (const float*)d_in[1];
    const float* att  = (const float*)d_in[2];

    cudaFuncSetAttribute(gemm_exp_kernel,
                         cudaFuncAttributeMaxDynamicSharedMemorySize, SMEM_TOTAL);

    prep_kernel<<<BATCH / 8, 256>>>(emb1, emb2, att);
    gemm_exp_kernel<<<NTRI, 256, SMEM_TOTAL>>>();
    final_kernel<<<1, 1024>>>((float*)d_out);
}